// round 1
// baseline (speedup 1.0000x reference)
#include <cuda_runtime.h>
#include <math.h>

#define Bc 2
#define Vc 5
#define Cc 32
#define Hc 128
#define Wc 160
#define Dc 32
#define Gc 8
#define HWc (Hc*Wc)            // 20480
#define BHW (Bc*HWc)           // 40960
#define BDHW (Bc*Dc*HWc)       // 1310720
#define SIMN (Bc*Gc*Dc*HWc)    // 10485760

// ---------------- scratch (device globals: no allocation allowed) ----------
__device__ float g_simbuf[SIMN];      // per-view sim (B,G,D,H,W)
__device__ float g_simsum[SIMN];      // weighted sim accumulator
__device__ float g_sbuf[BDHW];        // per-voxel MLP sigmoid output
__device__ float g_wsum[BHW];         // sum of view weights
__device__ float g_proj[(Vc-1)*Bc][12];  // per (v,b): R row-major (9) + t (3)

// ---------------- constant weights ----------------
__constant__ float c_rw1[8*8*27];
__constant__ float c_rb1[8];
__constant__ float c_rw2[8*27];
__constant__ float c_rb2[1];
__constant__ float c_pw1[16];
__constant__ float c_pb1[16];
__constant__ float c_pw2[8*16];
__constant__ float c_pb2[8];
__constant__ float c_pw3[8];
__constant__ float c_pb3[1];

// ---------------- projection setup ----------------
__device__ void combine_mat(const float* pm, double out[16]) {
    // pm -> (2,4,4): ext then K.  out = ext with out[:3,:4] = K[:3,:3] @ ext[:3,:4]
    const float* e = pm;
    const float* K = pm + 16;
    for (int r = 0; r < 4; r++)
        for (int c = 0; c < 4; c++)
            out[r*4+c] = (double)e[r*4+c];
    for (int r = 0; r < 3; r++)
        for (int c = 0; c < 4; c++) {
            double s = 0.0;
            for (int k = 0; k < 3; k++) s += (double)K[r*4+k] * (double)e[k*4+c];
            out[r*4+c] = s;
        }
}

__device__ void inv4(const double A[16], double Out[16]) {
    double a[4][8];
    for (int r = 0; r < 4; r++) {
        for (int c = 0; c < 4; c++) { a[r][c] = A[r*4+c]; a[r][c+4] = (r == c) ? 1.0 : 0.0; }
    }
    for (int col = 0; col < 4; col++) {
        int piv = col; double best = fabs(a[col][col]);
        for (int r = col+1; r < 4; r++) { double v = fabs(a[r][col]); if (v > best) { best = v; piv = r; } }
        if (piv != col)
            for (int c = 0; c < 8; c++) { double t = a[col][c]; a[col][c] = a[piv][c]; a[piv][c] = t; }
        double d = 1.0 / a[col][col];
        for (int c = 0; c < 8; c++) a[col][c] *= d;
        for (int r = 0; r < 4; r++) {
            if (r == col) continue;
            double f = a[r][col];
            for (int c = 0; c < 8; c++) a[r][c] -= f * a[col][c];
        }
    }
    for (int r = 0; r < 4; r++)
        for (int c = 0; c < 4; c++) Out[r*4+c] = a[r][c+4];
}

__global__ void proj_kernel(const float* __restrict__ pm) {
    if (threadIdx.x != 0 || blockIdx.x != 0) return;
    for (int b = 0; b < Bc; b++) {
        double ref[16], ri[16];
        combine_mat(pm + ((size_t)b*Vc + 0)*32, ref);
        inv4(ref, ri);
        for (int v = 1; v < Vc; v++) {
            double Cm[16];
            combine_mat(pm + ((size_t)b*Vc + v)*32, Cm);
            float* P = g_proj[(v-1)*Bc + b];
            for (int r = 0; r < 3; r++) {
                for (int c = 0; c < 4; c++) {
                    double s = 0.0;
                    for (int k = 0; k < 4; k++) s += Cm[r*4+k] * ri[k*4+c];
                    if (c < 3) P[r*3+c] = (float)s;
                    else       P[9+r]  = (float)s;
                }
            }
        }
    }
}

// ---------------- warp + group correlation + entropy MLP -------------------
__global__ void warp_sim_kernel(const float* __restrict__ features,
                                const float* __restrict__ dv,
                                int v) {
    int w = blockIdx.x * 16 + threadIdx.x;
    int h = blockIdx.y * 16 + threadIdx.y;
    int z = blockIdx.z;
    int b = z / Dc, d = z % Dc;

    const float* P = g_proj[(v-1)*Bc + b];
    float xf = (float)w, yf = (float)h;
    float rx = P[0]*xf + P[1]*yf + P[2];
    float ry = P[3]*xf + P[4]*yf + P[5];
    float rz = P[6]*xf + P[7]*yf + P[8];

    float dep = dv[((size_t)(b*Dc + d)*Hc + h)*Wc + w];
    float px = rx*dep + P[9];
    float py = ry*dep + P[10];
    float pz = rz*dep + P[11];
    float iz = 1.0f / pz;
    float x = px * iz;
    float y = py * iz;

    float x0f = floorf(x), y0f = floorf(y);
    float wx1 = x - x0f, wy1 = y - y0f;
    float wx0 = 1.0f - wx1, wy0 = 1.0f - wy1;
    float x1f = x0f + 1.0f, y1f = y0f + 1.0f;

    float v00 = (x0f >= 0.f && x0f <= (float)(Wc-1) && y0f >= 0.f && y0f <= (float)(Hc-1)) ? 1.f : 0.f;
    float v10 = (x1f >= 0.f && x1f <= (float)(Wc-1) && y0f >= 0.f && y0f <= (float)(Hc-1)) ? 1.f : 0.f;
    float v01 = (x0f >= 0.f && x0f <= (float)(Wc-1) && y1f >= 0.f && y1f <= (float)(Hc-1)) ? 1.f : 0.f;
    float v11 = (x1f >= 0.f && x1f <= (float)(Wc-1) && y1f >= 0.f && y1f <= (float)(Hc-1)) ? 1.f : 0.f;

    int x0 = (int)x0f; x0 = min(max(x0, 0), Wc-1);
    int y0 = (int)y0f; y0 = min(max(y0, 0), Hc-1);
    int x1 = (int)x1f; x1 = min(max(x1, 0), Wc-1);
    int y1 = (int)y1f; y1 = min(max(y1, 0), Hc-1);

    float a00 = wx0*wy0*v00;
    float a10 = wx1*wy0*v10;
    float a01 = wx0*wy1*v01;
    float a11 = wx1*wy1*v11;

    int o00 = y0*Wc + x0;
    int o10 = y0*Wc + x1;
    int o01 = y1*Wc + x0;
    int o11 = y1*Wc + x1;

    const float* fs = features + ((size_t)v*Bc + b)*Cc*HWc;
    const float* fr = features + ((size_t)b)*Cc*HWc + h*Wc + w;

    float acc[Gc];
    #pragma unroll
    for (int g = 0; g < Gc; g++) acc[g] = 0.0f;

    #pragma unroll
    for (int c = 0; c < Cc; c++) {
        const float* fc = fs + (size_t)c*HWc;
        float s = a00*fc[o00] + a10*fc[o10] + a01*fc[o01] + a11*fc[o11];
        float r = fr[(size_t)c*HWc];
        acc[c >> 2] += s * r;
    }

    float sim[Gc];
    size_t pbase = (size_t)h*Wc + w;
    #pragma unroll
    for (int g = 0; g < Gc; g++) {
        sim[g] = acc[g] * 0.25f;
        g_simbuf[(((size_t)(b*Gc + g)*Dc + d))*HWc + pbase] = sim[g];
    }

    // softmax over G + entropy
    float m = sim[0];
    #pragma unroll
    for (int g = 1; g < Gc; g++) m = fmaxf(m, sim[g]);
    float ssum = 0.0f;
    float ex[Gc];
    #pragma unroll
    for (int g = 0; g < Gc; g++) { ex[g] = expf(sim[g] - m); ssum += ex[g]; }
    float inv_s = 1.0f / ssum;
    float ent = 0.0f;
    #pragma unroll
    for (int g = 0; g < Gc; g++) {
        float p = ex[g] * inv_s;
        ent -= p * logf(p + 1e-7f);
    }

    // 1 -> 16 -> 8 -> 1 MLP + sigmoid
    float h1[16];
    #pragma unroll
    for (int j = 0; j < 16; j++) h1[j] = fmaxf(c_pw1[j]*ent + c_pb1[j], 0.0f);
    float h2[8];
    #pragma unroll
    for (int k = 0; k < 8; k++) {
        float t = c_pb2[k];
        #pragma unroll
        for (int j = 0; j < 16; j++) t += c_pw2[k*16 + j] * h1[j];
        h2[k] = fmaxf(t, 0.0f);
    }
    float o3 = c_pb3[0];
    #pragma unroll
    for (int k = 0; k < 8; k++) o3 += c_pw3[k] * h2[k];
    float sg = 1.0f / (1.0f + expf(-o3));

    g_sbuf[((size_t)(b*Dc + d))*HWc + pbase] = sg;
}

// ---------------- view weight: max over D + wsum ---------------------------
__global__ void vw_kernel(float* __restrict__ out_vw, int v) {
    int p = blockIdx.x * blockDim.x + threadIdx.x;
    if (p >= BHW) return;
    int b = p / HWc, pix = p % HWc;
    float m = -1e30f;
    for (int d = 0; d < Dc; d++)
        m = fmaxf(m, g_sbuf[((size_t)(b*Dc + d))*HWc + pix]);
    out_vw[((size_t)b*(Vc-1) + (v-1))*HWc + pix] = m;
    g_wsum[p] = (v == 1) ? m : (g_wsum[p] + m);
}

// ---------------- accumulate sim * vw --------------------------------------
__global__ void acc_kernel(const float* __restrict__ vwbuf, int v) {
    size_t idx = (size_t)blockIdx.x * blockDim.x + threadIdx.x;
    if (idx >= SIMN) return;
    int pix = (int)(idx % HWc);
    int b = (int)(idx / ((size_t)Gc*Dc*HWc));
    float vw = vwbuf[((size_t)b*(Vc-1) + (v-1))*HWc + pix];
    float val = g_simbuf[idx] * vw;
    g_simsum[idx] = (v == 1) ? val : (g_simsum[idx] + val);
}

// ---------------- similarity = sim_sum / (w_sum + eps) ---------------------
__global__ void simdiv_kernel(float* __restrict__ out_sim) {
    size_t idx = (size_t)blockIdx.x * blockDim.x + threadIdx.x;
    if (idx >= SIMN) return;
    int pix = (int)(idx % HWc);
    int b = (int)(idx / ((size_t)Gc*Dc*HWc));
    out_sim[idx] = g_simsum[idx] / (g_wsum[b*HWc + pix] + 1e-6f);
}

// ---------------- conv3d 8->8, 3x3x3, pad 1, relu --------------------------
__global__ void conv1_kernel(const float* __restrict__ simil) {
    int w = blockIdx.x * 16 + threadIdx.x;
    int h = blockIdx.y * 16 + threadIdx.y;
    int z = blockIdx.z;
    int b = z / Dc, d = z % Dc;

    float acc[8];
    #pragma unroll
    for (int o = 0; o < 8; o++) acc[o] = c_rb1[o];

    const float* base = simil + (size_t)b*Gc*Dc*HWc;
    #pragma unroll
    for (int i = 0; i < 8; i++) {
        #pragma unroll
        for (int kd = 0; kd < 3; kd++) {
            int dd = d + kd - 1;
            if ((unsigned)dd >= (unsigned)Dc) continue;
            const float* plane = base + ((size_t)i*Dc + dd)*HWc;
            #pragma unroll
            for (int kh = 0; kh < 3; kh++) {
                int hh = h + kh - 1;
                if ((unsigned)hh >= (unsigned)Hc) continue;
                #pragma unroll
                for (int kw = 0; kw < 3; kw++) {
                    int ww = w + kw - 1;
                    if ((unsigned)ww >= (unsigned)Wc) continue;
                    float x = plane[hh*Wc + ww];
                    int widx = i*27 + kd*9 + kh*3 + kw;
                    #pragma unroll
                    for (int o = 0; o < 8; o++)
                        acc[o] += x * c_rw1[o*216 + widx];
                }
            }
        }
    }
    size_t pbase = (size_t)h*Wc + w;
    #pragma unroll
    for (int o = 0; o < 8; o++)
        g_simbuf[(((size_t)(b*8 + o)*Dc + d))*HWc + pbase] = fmaxf(acc[o], 0.0f);
}

// ---------------- conv3d 8->1, 3x3x3, pad 1 --------------------------------
__global__ void conv2_kernel(float* __restrict__ out_pvp) {
    int w = blockIdx.x * 16 + threadIdx.x;
    int h = blockIdx.y * 16 + threadIdx.y;
    int z = blockIdx.z;
    int b = z / Dc, d = z % Dc;

    float acc = c_rb2[0];
    #pragma unroll
    for (int i = 0; i < 8; i++) {
        #pragma unroll
        for (int kd = 0; kd < 3; kd++) {
            int dd = d + kd - 1;
            if ((unsigned)dd >= (unsigned)Dc) continue;
            const float* plane = g_simbuf + ((size_t)(b*8 + i)*Dc + dd)*HWc;
            #pragma unroll
            for (int kh = 0; kh < 3; kh++) {
                int hh = h + kh - 1;
                if ((unsigned)hh >= (unsigned)Hc) continue;
                #pragma unroll
                for (int kw = 0; kw < 3; kw++) {
                    int ww = w + kw - 1;
                    if ((unsigned)ww >= (unsigned)Wc) continue;
                    acc += plane[hh*Wc + ww] * c_rw2[i*27 + kd*9 + kh*3 + kw];
                }
            }
        }
    }
    out_pvp[((size_t)(b*Dc + d))*HWc + (size_t)h*Wc + w] = acc;
}

// ---------------- depth softmax + expectation + confidence -----------------
__global__ void final_kernel(const float* __restrict__ pvp,
                             const float* __restrict__ dv,
                             float* __restrict__ depth_out,
                             float* __restrict__ conf_out) {
    int p = blockIdx.x * blockDim.x + threadIdx.x;
    if (p >= BHW) return;
    int b = p / HWc, pix = p % HWc;
    const float* vp = pvp + (size_t)b*Dc*HWc + pix;
    const float* dvp = dv + (size_t)b*Dc*HWc + pix;

    float x[Dc];
    float m = -1e30f;
    #pragma unroll
    for (int d = 0; d < Dc; d++) { x[d] = vp[(size_t)d*HWc]; m = fmaxf(m, x[d]); }
    float s = 0.0f;
    #pragma unroll
    for (int d = 0; d < Dc; d++) { x[d] = expf(x[d] - m); s += x[d]; }
    float inv_s = 1.0f / s;
    float depth = 0.0f, dif = 0.0f;
    #pragma unroll
    for (int d = 0; d < Dc; d++) {
        float pd = x[d] * inv_s;
        x[d] = pd;
        depth += pd * dvp[(size_t)d*HWc];
        dif += pd * (float)d;
    }
    int di = (int)dif;
    di = min(max(di, 0), Dc-1);
    float c4 = 0.0f;
    #pragma unroll
    for (int d = 0; d < Dc; d++) {
        bool in = (d >= di - 1) && (d <= di + 2);
        c4 += in ? x[d] : 0.0f;
    }
    depth_out[p] = depth;
    conf_out[p] = c4;
}

// ---------------- launch ----------------------------------------------------
extern "C" void kernel_launch(void* const* d_in, const int* in_sizes, int n_in,
                              void* d_out, int out_size) {
    const float* features = (const float*)d_in[0];
    const float* pm       = (const float*)d_in[1];
    const float* dv       = (const float*)d_in[2];

    cudaMemcpyToSymbolAsync(c_rw1, d_in[3], 8*8*27*sizeof(float), 0, cudaMemcpyDeviceToDevice);
    cudaMemcpyToSymbolAsync(c_rb1, d_in[4], 8*sizeof(float),      0, cudaMemcpyDeviceToDevice);
    cudaMemcpyToSymbolAsync(c_rw2, d_in[5], 8*27*sizeof(float),   0, cudaMemcpyDeviceToDevice);
    cudaMemcpyToSymbolAsync(c_rb2, d_in[6], 1*sizeof(float),      0, cudaMemcpyDeviceToDevice);
    cudaMemcpyToSymbolAsync(c_pw1, d_in[7], 16*sizeof(float),     0, cudaMemcpyDeviceToDevice);
    cudaMemcpyToSymbolAsync(c_pb1, d_in[8], 16*sizeof(float),     0, cudaMemcpyDeviceToDevice);
    cudaMemcpyToSymbolAsync(c_pw2, d_in[9], 8*16*sizeof(float),   0, cudaMemcpyDeviceToDevice);
    cudaMemcpyToSymbolAsync(c_pb2, d_in[10], 8*sizeof(float),     0, cudaMemcpyDeviceToDevice);
    cudaMemcpyToSymbolAsync(c_pw3, d_in[11], 8*sizeof(float),     0, cudaMemcpyDeviceToDevice);
    cudaMemcpyToSymbolAsync(c_pb3, d_in[12], 1*sizeof(float),     0, cudaMemcpyDeviceToDevice);

    float* out       = (float*)d_out;
    float* out_depth = out;
    float* out_conf  = out + BHW;
    float* out_vw    = out + 2*BHW;
    float* out_pvp   = out + 2*BHW + (Vc-1)*BHW;          // 6*BHW
    float* out_sim   = out_pvp + BDHW;

    proj_kernel<<<1, 32>>>(pm);

    dim3 blk(16, 16);
    dim3 grd(Wc/16, Hc/16, Bc*Dc);

    for (int v = 1; v < Vc; v++) {
        warp_sim_kernel<<<grd, blk>>>(features, dv, v);
        vw_kernel<<<(BHW + 255)/256, 256>>>(out_vw, v);
        acc_kernel<<<(SIMN + 255)/256, 256>>>(out_vw, v);
    }

    simdiv_kernel<<<(SIMN + 255)/256, 256>>>(out_sim);
    conv1_kernel<<<grd, blk>>>(out_sim);
    conv2_kernel<<<grd, blk>>>(out_pvp);
    final_kernel<<<(BHW + 255)/256, 256>>>(out_pvp, dv, out_depth, out_conf);
}

// round 2
// speedup vs baseline: 3.1377x; 3.1377x over previous
#include <cuda_runtime.h>
#include <math.h>

#define Bc 2
#define Vc 5
#define Cc 32
#define Hc 128
#define Wc 160
#define Dc 32
#define Gc 8
#define HWc (Hc*Wc)            // 20480
#define BHW (Bc*HWc)           // 40960
#define BDHW (Bc*Dc*HWc)       // 1310720
#define SIMN (Bc*Gc*Dc*HWc)    // 10485760

// ---------------- scratch (device globals: no allocation allowed) ----------
__device__ float g_sim[Vc-1][SIMN];      // per-view sim (B,G,D,H,W)  (~168MB)
__device__ float g_feat[(size_t)Vc*Bc*HWc*Cc];  // transposed features (V,B,HW,C)
__device__ float g_proj[(Vc-1)*Bc][12];  // per (v,b): R row-major (9) + t (3)
// conv1 output reuses g_sim[0] (free after combine)

// ---------------- constant weights ----------------
__constant__ float c_rw1[8*8*27];
__constant__ float c_rb1[8];
__constant__ float c_rw2[8*27];
__constant__ float c_rb2[1];
__constant__ float c_pw1[16];
__constant__ float c_pb1[16];
__constant__ float c_pw2[8*16];
__constant__ float c_pb2[8];
__constant__ float c_pw3[8];
__constant__ float c_pb3[1];

// ---------------- projection setup ----------------
__device__ void combine_mat(const float* pm, double out[16]) {
    const float* e = pm;
    const float* K = pm + 16;
    for (int r = 0; r < 4; r++)
        for (int c = 0; c < 4; c++)
            out[r*4+c] = (double)e[r*4+c];
    for (int r = 0; r < 3; r++)
        for (int c = 0; c < 4; c++) {
            double s = 0.0;
            for (int k = 0; k < 3; k++) s += (double)K[r*4+k] * (double)e[k*4+c];
            out[r*4+c] = s;
        }
}

__device__ void inv4(const double A[16], double Out[16]) {
    double a[4][8];
    for (int r = 0; r < 4; r++)
        for (int c = 0; c < 4; c++) { a[r][c] = A[r*4+c]; a[r][c+4] = (r == c) ? 1.0 : 0.0; }
    for (int col = 0; col < 4; col++) {
        int piv = col; double best = fabs(a[col][col]);
        for (int r = col+1; r < 4; r++) { double v = fabs(a[r][col]); if (v > best) { best = v; piv = r; } }
        if (piv != col)
            for (int c = 0; c < 8; c++) { double t = a[col][c]; a[col][c] = a[piv][c]; a[piv][c] = t; }
        double d = 1.0 / a[col][col];
        for (int c = 0; c < 8; c++) a[col][c] *= d;
        for (int r = 0; r < 4; r++) {
            if (r == col) continue;
            double f = a[r][col];
            for (int c = 0; c < 8; c++) a[r][c] -= f * a[col][c];
        }
    }
    for (int r = 0; r < 4; r++)
        for (int c = 0; c < 4; c++) Out[r*4+c] = a[r][c+4];
}

__global__ void proj_kernel(const float* __restrict__ pm) {
    if (threadIdx.x != 0 || blockIdx.x != 0) return;
    for (int b = 0; b < Bc; b++) {
        double ref[16], ri[16];
        combine_mat(pm + ((size_t)b*Vc + 0)*32, ref);
        inv4(ref, ri);
        for (int v = 1; v < Vc; v++) {
            double Cm[16];
            combine_mat(pm + ((size_t)b*Vc + v)*32, Cm);
            float* P = g_proj[(v-1)*Bc + b];
            for (int r = 0; r < 3; r++) {
                for (int c = 0; c < 4; c++) {
                    double s = 0.0;
                    for (int k = 0; k < 4; k++) s += Cm[r*4+k] * ri[k*4+c];
                    if (c < 3) P[r*3+c] = (float)s;
                    else       P[9+r]  = (float)s;
                }
            }
        }
    }
}

// ---------------- feature transpose (V,B,C,HW) -> (V,B,HW,C) ---------------
__global__ void transpose_kernel(const float* __restrict__ f) {
    __shared__ float t[32][33];
    int vb  = blockIdx.y;
    int hw0 = blockIdx.x * 32;
    t[threadIdx.y][threadIdx.x] =
        f[((size_t)vb*Cc + threadIdx.y)*HWc + hw0 + threadIdx.x];
    __syncthreads();
    g_feat[((size_t)vb*HWc + hw0 + threadIdx.y)*Cc + threadIdx.x] =
        t[threadIdx.x][threadIdx.y];
}

// ------- fused warp + group correlation + entropy MLP + vw(max over D) -----
__global__ void __launch_bounds__(256) warp_sim_kernel(const float* __restrict__ dv,
                                                       float* __restrict__ out_vw) {
    int pix = blockIdx.x * 256 + threadIdx.x;
    int b = blockIdx.y;
    int v = blockIdx.z + 1;
    int w = pix % Wc, h = pix / Wc;

    const float* P = g_proj[(v-1)*Bc + b];
    float xf = (float)w, yf = (float)h;
    float rx = P[0]*xf + P[1]*yf + P[2];
    float ry = P[3]*xf + P[4]*yf + P[5];
    float rz = P[6]*xf + P[7]*yf + P[8];

    // reference feature: 32 contiguous channels
    const float4* refp = (const float4*)(g_feat + ((size_t)b*HWc + pix)*Cc);
    float4 rf[8];
    #pragma unroll
    for (int c4 = 0; c4 < 8; c4++) rf[c4] = refp[c4];

    const float* fsv = g_feat + ((size_t)(v*Bc + b)*HWc)*Cc;
    float* gs = g_sim[v-1] + (size_t)b*Gc*Dc*HWc + pix;

    float vmax = -1e30f;

    #pragma unroll 1
    for (int d = 0; d < Dc; d++) {
        float dep = dv[((size_t)(b*Dc + d))*HWc + pix];
        float px = rx*dep + P[9];
        float py = ry*dep + P[10];
        float pz = rz*dep + P[11];
        float iz = 1.0f / pz;
        float x = px * iz;
        float y = py * iz;

        float x0f = floorf(x), y0f = floorf(y);
        float wx1 = x - x0f, wy1 = y - y0f;
        float wx0 = 1.0f - wx1, wy0 = 1.0f - wy1;
        float x1f = x0f + 1.0f, y1f = y0f + 1.0f;

        float vx0 = (x0f >= 0.f && x0f <= (float)(Wc-1)) ? 1.f : 0.f;
        float vx1 = (x1f >= 0.f && x1f <= (float)(Wc-1)) ? 1.f : 0.f;
        float vy0 = (y0f >= 0.f && y0f <= (float)(Hc-1)) ? 1.f : 0.f;
        float vy1 = (y1f >= 0.f && y1f <= (float)(Hc-1)) ? 1.f : 0.f;

        int x0 = min(max((int)x0f, 0), Wc-1);
        int y0 = min(max((int)y0f, 0), Hc-1);
        int x1 = min(max((int)x1f, 0), Wc-1);
        int y1 = min(max((int)y1f, 0), Hc-1);

        float a00 = wx0*wy0*vx0*vy0;
        float a10 = wx1*wy0*vx1*vy0;
        float a01 = wx0*wy1*vx0*vy1;
        float a11 = wx1*wy1*vx1*vy1;

        const float4* p00 = (const float4*)(fsv + (size_t)(y0*Wc + x0)*Cc);
        const float4* p10 = (const float4*)(fsv + (size_t)(y0*Wc + x1)*Cc);
        const float4* p01 = (const float4*)(fsv + (size_t)(y1*Wc + x0)*Cc);
        const float4* p11 = (const float4*)(fsv + (size_t)(y1*Wc + x1)*Cc);

        float sim[8];
        #pragma unroll
        for (int c4 = 0; c4 < 8; c4++) {
            float4 f00 = p00[c4], f10 = p10[c4], f01 = p01[c4], f11 = p11[c4];
            float sx = a00*f00.x + a10*f10.x + a01*f01.x + a11*f11.x;
            float sy = a00*f00.y + a10*f10.y + a01*f01.y + a11*f11.y;
            float sz = a00*f00.z + a10*f10.z + a01*f01.z + a11*f11.z;
            float sw = a00*f00.w + a10*f10.w + a01*f01.w + a11*f11.w;
            float4 r = rf[c4];
            sim[c4] = (sx*r.x + sy*r.y + sz*r.z + sw*r.w) * 0.25f;
        }

        #pragma unroll
        for (int g = 0; g < 8; g++)
            gs[((size_t)g*Dc + d)*HWc] = sim[g];

        // softmax over G + entropy
        float m = sim[0];
        #pragma unroll
        for (int g = 1; g < 8; g++) m = fmaxf(m, sim[g]);
        float ssum = 0.0f;
        float ex[8];
        #pragma unroll
        for (int g = 0; g < 8; g++) { ex[g] = expf(sim[g] - m); ssum += ex[g]; }
        float inv_s = 1.0f / ssum;
        float ent = 0.0f;
        #pragma unroll
        for (int g = 0; g < 8; g++) {
            float p = ex[g] * inv_s;
            ent -= p * logf(p + 1e-7f);
        }

        // 1 -> 16 -> 8 -> 1 MLP + sigmoid
        float h1[16];
        #pragma unroll
        for (int j = 0; j < 16; j++) h1[j] = fmaxf(c_pw1[j]*ent + c_pb1[j], 0.0f);
        float h2[8];
        #pragma unroll
        for (int k = 0; k < 8; k++) {
            float t = c_pb2[k];
            #pragma unroll
            for (int j = 0; j < 16; j++) t += c_pw2[k*16 + j] * h1[j];
            h2[k] = fmaxf(t, 0.0f);
        }
        float o3 = c_pb3[0];
        #pragma unroll
        for (int k = 0; k < 8; k++) o3 += c_pw3[k] * h2[k];
        float sg = 1.0f / (1.0f + expf(-o3));
        vmax = fmaxf(vmax, sg);
    }

    out_vw[((size_t)b*(Vc-1) + (v-1))*HWc + pix] = vmax;
}

// -------- combine: out_sim = sum_v sim_v*vw_v / (sum_v vw_v + eps) ---------
__global__ void combine_kernel(const float* __restrict__ vwbuf,
                               float* __restrict__ out_sim) {
    size_t i4 = (size_t)blockIdx.x * blockDim.x + threadIdx.x;
    if (i4 >= SIMN/4) return;
    size_t idx = i4 * 4;
    int b   = (int)(idx / ((size_t)Gc*Dc*HWc));
    int pix = (int)(idx % HWc);

    float4 acc = make_float4(0.f, 0.f, 0.f, 0.f);
    float4 ws  = make_float4(0.f, 0.f, 0.f, 0.f);
    #pragma unroll
    for (int vi = 0; vi < Vc-1; vi++) {
        float4 vw = *(const float4*)&vwbuf[((size_t)b*(Vc-1) + vi)*HWc + pix];
        float4 s  = *(const float4*)&g_sim[vi][idx];
        acc.x += s.x*vw.x; acc.y += s.y*vw.y; acc.z += s.z*vw.z; acc.w += s.w*vw.w;
        ws.x += vw.x; ws.y += vw.y; ws.z += vw.z; ws.w += vw.w;
    }
    float4 o;
    o.x = acc.x / (ws.x + 1e-6f);
    o.y = acc.y / (ws.y + 1e-6f);
    o.z = acc.z / (ws.z + 1e-6f);
    o.w = acc.w / (ws.w + 1e-6f);
    *(float4*)&out_sim[idx] = o;
}

// ---------------- conv3d 8->8, 3x3x3, pad 1, relu (streaming d) ------------
#define CT 8   // tile size (CT x CT spatial)
__global__ void __launch_bounds__(CT*CT) conv1_kernel(const float* __restrict__ simil) {
    __shared__ float sl[8][CT+2][CT+2];
    int tx = threadIdx.x, ty = threadIdx.y;
    int w0 = blockIdx.x * CT, h0 = blockIdx.y * CT;
    int b = blockIdx.z;
    int tid = ty * CT + tx;

    const float* base = simil + (size_t)b*Gc*Dc*HWc;
    float* outb = g_sim[0] + (size_t)b*8*Dc*HWc;   // reuse as conv1 output

    float accP[8], accC[8], accN[8];
    #pragma unroll
    for (int o = 0; o < 8; o++) { accP[o] = 0.f; accC[o] = 0.f; accN[o] = 0.f; }

    #pragma unroll 1
    for (int s = 0; s < Dc; s++) {
        __syncthreads();
        // load slice s (8 ch, (CT+2)^2 halo)
        for (int idx = tid; idx < 8*(CT+2)*(CT+2); idx += CT*CT) {
            int i  = idx / ((CT+2)*(CT+2));
            int rm = idx % ((CT+2)*(CT+2));
            int hh = rm / (CT+2), ww = rm % (CT+2);
            int gh = h0 + hh - 1, gw = w0 + ww - 1;
            float val = 0.0f;
            if (gh >= 0 && gh < Hc && gw >= 0 && gw < Wc)
                val = base[((size_t)i*Dc + s)*HWc + gh*Wc + gw];
            sl[i][hh][ww] = val;
        }
        __syncthreads();

        #pragma unroll
        for (int i = 0; i < 8; i++) {
            #pragma unroll
            for (int kh = 0; kh < 3; kh++) {
                #pragma unroll
                for (int kw = 0; kw < 3; kw++) {
                    float x = sl[i][ty+kh][tx+kw];
                    int wb = i*27 + kh*3 + kw;
                    #pragma unroll
                    for (int o = 0; o < 8; o++) {
                        accN[o] += x * c_rw1[o*216 + wb];        // kd=0 -> out s+1
                        accC[o] += x * c_rw1[o*216 + wb + 9];    // kd=1 -> out s
                        accP[o] += x * c_rw1[o*216 + wb + 18];   // kd=2 -> out s-1
                    }
                }
            }
        }

        if (s >= 1) {
            size_t pb = (size_t)(s-1)*HWc + (h0+ty)*Wc + (w0+tx);
            #pragma unroll
            for (int o = 0; o < 8; o++)
                outb[(size_t)o*Dc*HWc + pb] = fmaxf(accP[o] + c_rb1[o], 0.0f);
        }
        #pragma unroll
        for (int o = 0; o < 8; o++) { accP[o] = accC[o]; accC[o] = accN[o]; accN[o] = 0.f; }
    }
    {
        size_t pb = (size_t)(Dc-1)*HWc + (h0+ty)*Wc + (w0+tx);
        #pragma unroll
        for (int o = 0; o < 8; o++)
            outb[(size_t)o*Dc*HWc + pb] = fmaxf(accP[o] + c_rb1[o], 0.0f);
    }
}

// ---------------- conv3d 8->1, 3x3x3, pad 1 (streaming d) ------------------
__global__ void __launch_bounds__(CT*CT) conv2_kernel(float* __restrict__ out_pvp) {
    __shared__ float sl[8][CT+2][CT+2];
    int tx = threadIdx.x, ty = threadIdx.y;
    int w0 = blockIdx.x * CT, h0 = blockIdx.y * CT;
    int b = blockIdx.z;
    int tid = ty * CT + tx;

    const float* base = g_sim[0] + (size_t)b*8*Dc*HWc;

    float accP = 0.f, accC = 0.f, accN = 0.f;

    #pragma unroll 1
    for (int s = 0; s < Dc; s++) {
        __syncthreads();
        for (int idx = tid; idx < 8*(CT+2)*(CT+2); idx += CT*CT) {
            int i  = idx / ((CT+2)*(CT+2));
            int rm = idx % ((CT+2)*(CT+2));
            int hh = rm / (CT+2), ww = rm % (CT+2);
            int gh = h0 + hh - 1, gw = w0 + ww - 1;
            float val = 0.0f;
            if (gh >= 0 && gh < Hc && gw >= 0 && gw < Wc)
                val = base[((size_t)i*Dc + s)*HWc + gh*Wc + gw];
            sl[i][hh][ww] = val;
        }
        __syncthreads();

        #pragma unroll
        for (int i = 0; i < 8; i++) {
            #pragma unroll
            for (int kh = 0; kh < 3; kh++) {
                #pragma unroll
                for (int kw = 0; kw < 3; kw++) {
                    float x = sl[i][ty+kh][tx+kw];
                    int wb = i*27 + kh*3 + kw;
                    accN += x * c_rw2[wb];
                    accC += x * c_rw2[wb + 9];
                    accP += x * c_rw2[wb + 18];
                }
            }
        }

        if (s >= 1)
            out_pvp[((size_t)b*Dc + (s-1))*HWc + (h0+ty)*Wc + (w0+tx)] = accP + c_rb2[0];
        accP = accC; accC = accN; accN = 0.f;
    }
    out_pvp[((size_t)b*Dc + (Dc-1))*HWc + (h0+ty)*Wc + (w0+tx)] = accP + c_rb2[0];
}

// ---------------- depth softmax + expectation + confidence -----------------
__global__ void final_kernel(const float* __restrict__ pvp,
                             const float* __restrict__ dv,
                             float* __restrict__ depth_out,
                             float* __restrict__ conf_out) {
    int p = blockIdx.x * blockDim.x + threadIdx.x;
    if (p >= BHW) return;
    int b = p / HWc, pix = p % HWc;
    const float* vp  = pvp + (size_t)b*Dc*HWc + pix;
    const float* dvp = dv  + (size_t)b*Dc*HWc + pix;

    float x[Dc];
    float m = -1e30f;
    #pragma unroll
    for (int d = 0; d < Dc; d++) { x[d] = vp[(size_t)d*HWc]; m = fmaxf(m, x[d]); }
    float s = 0.0f;
    #pragma unroll
    for (int d = 0; d < Dc; d++) { x[d] = expf(x[d] - m); s += x[d]; }
    float inv_s = 1.0f / s;
    float depth = 0.0f, dif = 0.0f;
    #pragma unroll
    for (int d = 0; d < Dc; d++) {
        float pd = x[d] * inv_s;
        x[d] = pd;
        depth += pd * dvp[(size_t)d*HWc];
        dif += pd * (float)d;
    }
    int di = min(max((int)dif, 0), Dc-1);
    float c4 = 0.0f;
    #pragma unroll
    for (int d = 0; d < Dc; d++) {
        bool in = (d >= di - 1) && (d <= di + 2);
        c4 += in ? x[d] : 0.0f;
    }
    depth_out[p] = depth;
    conf_out[p] = c4;
}

// ---------------- launch ----------------------------------------------------
extern "C" void kernel_launch(void* const* d_in, const int* in_sizes, int n_in,
                              void* d_out, int out_size) {
    const float* features = (const float*)d_in[0];
    const float* pm       = (const float*)d_in[1];
    const float* dv       = (const float*)d_in[2];

    cudaMemcpyToSymbolAsync(c_rw1, d_in[3], 8*8*27*sizeof(float), 0, cudaMemcpyDeviceToDevice);
    cudaMemcpyToSymbolAsync(c_rb1, d_in[4], 8*sizeof(float),      0, cudaMemcpyDeviceToDevice);
    cudaMemcpyToSymbolAsync(c_rw2, d_in[5], 8*27*sizeof(float),   0, cudaMemcpyDeviceToDevice);
    cudaMemcpyToSymbolAsync(c_rb2, d_in[6], 1*sizeof(float),      0, cudaMemcpyDeviceToDevice);
    cudaMemcpyToSymbolAsync(c_pw1, d_in[7], 16*sizeof(float),     0, cudaMemcpyDeviceToDevice);
    cudaMemcpyToSymbolAsync(c_pb1, d_in[8], 16*sizeof(float),     0, cudaMemcpyDeviceToDevice);
    cudaMemcpyToSymbolAsync(c_pw2, d_in[9], 8*16*sizeof(float),   0, cudaMemcpyDeviceToDevice);
    cudaMemcpyToSymbolAsync(c_pb2, d_in[10], 8*sizeof(float),     0, cudaMemcpyDeviceToDevice);
    cudaMemcpyToSymbolAsync(c_pw3, d_in[11], 8*sizeof(float),     0, cudaMemcpyDeviceToDevice);
    cudaMemcpyToSymbolAsync(c_pb3, d_in[12], 1*sizeof(float),     0, cudaMemcpyDeviceToDevice);

    float* out       = (float*)d_out;
    float* out_depth = out;
    float* out_conf  = out + BHW;
    float* out_vw    = out + 2*BHW;
    float* out_pvp   = out + 2*BHW + (Vc-1)*BHW;          // 6*BHW
    float* out_sim   = out_pvp + BDHW;

    proj_kernel<<<1, 32>>>(pm);

    {   // transpose features to channel-contiguous layout
        dim3 blk(32, 32);
        dim3 grd(HWc/32, Vc*Bc);
        transpose_kernel<<<grd, blk>>>(features);
    }

    {   // fused warp + sim + entropy MLP + view weight, all views in one launch
        dim3 blk(256);
        dim3 grd(HWc/256, Bc, Vc-1);
        warp_sim_kernel<<<grd, blk>>>(dv, out_vw);
    }

    combine_kernel<<<(SIMN/4 + 255)/256, 256>>>(out_vw, out_sim);

    {
        dim3 blk(CT, CT);
        dim3 grd(Wc/CT, Hc/CT, Bc);
        conv1_kernel<<<grd, blk>>>(out_sim);
        conv2_kernel<<<grd, blk>>>(out_pvp);
    }

    final_kernel<<<(BHW + 255)/256, 256>>>(out_pvp, dv, out_depth, out_conf);
}

// round 3
// speedup vs baseline: 3.3561x; 1.0696x over previous
#include <cuda_runtime.h>
#include <math.h>

#define Bc 2
#define Vc 5
#define Cc 32
#define Hc 128
#define Wc 160
#define Dc 32
#define Gc 8
#define HWc (Hc*Wc)            // 20480
#define BHW (Bc*HWc)           // 40960
#define BDHW (Bc*Dc*HWc)       // 1310720
#define SIMN (Bc*Gc*Dc*HWc)    // 10485760

// ---------------- scratch (device globals: no allocation allowed) ----------
__device__ float g_sim[Vc-1][SIMN];              // per-view sim (B,G,D,H,W)
__device__ float g_feat[(size_t)Vc*Bc*Cc*HWc];   // transposed features (V,B,G,HW,4)
__device__ float g_proj[(Vc-1)*Bc][12];          // per (v,b): R (9) + t (3)
// conv1 output reuses g_sim[0] (free after combine)

// ---------------- constant weights ----------------
__constant__ float c_rw1[8*8*27];
__constant__ float c_rb1[8];
__constant__ float c_rw2[8*27];
__constant__ float c_rb2[1];
__constant__ float c_pw1[16];
__constant__ float c_pb1[16];
__constant__ float c_pw2[8*16];
__constant__ float c_pb2[8];
__constant__ float c_pw3[8];
__constant__ float c_pb3[1];

// ---------------- projection setup ----------------
__device__ void combine_mat(const float* pm, double out[16]) {
    const float* e = pm;
    const float* K = pm + 16;
    for (int r = 0; r < 4; r++)
        for (int c = 0; c < 4; c++)
            out[r*4+c] = (double)e[r*4+c];
    for (int r = 0; r < 3; r++)
        for (int c = 0; c < 4; c++) {
            double s = 0.0;
            for (int k = 0; k < 3; k++) s += (double)K[r*4+k] * (double)e[k*4+c];
            out[r*4+c] = s;
        }
}

__device__ void inv4(const double A[16], double Out[16]) {
    double a[4][8];
    for (int r = 0; r < 4; r++)
        for (int c = 0; c < 4; c++) { a[r][c] = A[r*4+c]; a[r][c+4] = (r == c) ? 1.0 : 0.0; }
    for (int col = 0; col < 4; col++) {
        int piv = col; double best = fabs(a[col][col]);
        for (int r = col+1; r < 4; r++) { double v = fabs(a[r][col]); if (v > best) { best = v; piv = r; } }
        if (piv != col)
            for (int c = 0; c < 8; c++) { double t = a[col][c]; a[col][c] = a[piv][c]; a[piv][c] = t; }
        double d = 1.0 / a[col][col];
        for (int c = 0; c < 8; c++) a[col][c] *= d;
        for (int r = 0; r < 4; r++) {
            if (r == col) continue;
            double f = a[r][col];
            for (int c = 0; c < 8; c++) a[r][c] -= f * a[col][c];
        }
    }
    for (int r = 0; r < 4; r++)
        for (int c = 0; c < 4; c++) Out[r*4+c] = a[r][c+4];
}

__global__ void proj_kernel(const float* __restrict__ pm) {
    if (threadIdx.x != 0 || blockIdx.x != 0) return;
    for (int b = 0; b < Bc; b++) {
        double ref[16], ri[16];
        combine_mat(pm + ((size_t)b*Vc + 0)*32, ref);
        inv4(ref, ri);
        for (int v = 1; v < Vc; v++) {
            double Cm[16];
            combine_mat(pm + ((size_t)b*Vc + v)*32, Cm);
            float* P = g_proj[(v-1)*Bc + b];
            for (int r = 0; r < 3; r++) {
                for (int c = 0; c < 4; c++) {
                    double s = 0.0;
                    for (int k = 0; k < 4; k++) s += Cm[r*4+k] * ri[k*4+c];
                    if (c < 3) P[r*3+c] = (float)s;
                    else       P[9+r]  = (float)s;
                }
            }
        }
    }
}

// --------- feature transpose (V,B,C,HW) -> (V,B,G,HW,4) float4 groups -----
__global__ void __launch_bounds__(256) transpose_kernel(const float* __restrict__ f) {
    __shared__ float t[32][33];
    int vb  = blockIdx.y;
    int hw0 = blockIdx.x * 32;
    int tid = threadIdx.x;
    #pragma unroll
    for (int i = 0; i < 4; i++) {
        int idx = tid + i*256;
        int ch = idx / 32, hw = idx % 32;
        t[ch][hw] = f[((size_t)vb*Cc + ch)*HWc + hw0 + hw];
    }
    __syncthreads();
    int g = tid / 32, hw = tid % 32;
    float4 o = make_float4(t[4*g+0][hw], t[4*g+1][hw], t[4*g+2][hw], t[4*g+3][hw]);
    ((float4*)g_feat)[((size_t)vb*Gc + g)*HWc + hw0 + hw] = o;
}

// ------- fused warp + group correlation + entropy MLP + vw(max over D) -----
__global__ void __launch_bounds__(256) warp_sim_kernel(const float* __restrict__ dv,
                                                       float* __restrict__ out_vw) {
    int pix = blockIdx.x * 256 + threadIdx.x;
    int b = blockIdx.y;
    int v = blockIdx.z + 1;
    int w = pix % Wc, h = pix / Wc;

    const float* P = g_proj[(v-1)*Bc + b];
    float xf = (float)w, yf = (float)h;
    float rx = P[0]*xf + P[1]*yf + P[2];
    float ry = P[3]*xf + P[4]*yf + P[5];
    float rz = P[6]*xf + P[7]*yf + P[8];

    // reference feature: 8 group-float4s, coalesced across warp
    const float4* refb = ((const float4*)g_feat) + (size_t)b*Gc*HWc + pix;
    float4 rf[8];
    #pragma unroll
    for (int g = 0; g < 8; g++) rf[g] = refb[(size_t)g*HWc];

    const float4* fbase = ((const float4*)g_feat) + (size_t)(v*Bc + b)*Gc*HWc;
    float* gs = g_sim[v-1] + (size_t)b*Gc*Dc*HWc + pix;

    float o3max = -1e30f;

    #pragma unroll 1
    for (int d = 0; d < Dc; d++) {
        float dep = dv[((size_t)(b*Dc + d))*HWc + pix];
        float px = rx*dep + P[9];
        float py = ry*dep + P[10];
        float pz = rz*dep + P[11];
        float iz = 1.0f / pz;
        float x = px * iz;
        float y = py * iz;

        float x0f = floorf(x), y0f = floorf(y);
        float wx1 = x - x0f, wy1 = y - y0f;
        float wx0 = 1.0f - wx1, wy0 = 1.0f - wy1;
        float x1f = x0f + 1.0f, y1f = y0f + 1.0f;

        float vx0 = (x0f >= 0.f && x0f <= (float)(Wc-1)) ? 1.f : 0.f;
        float vx1 = (x1f >= 0.f && x1f <= (float)(Wc-1)) ? 1.f : 0.f;
        float vy0 = (y0f >= 0.f && y0f <= (float)(Hc-1)) ? 1.f : 0.f;
        float vy1 = (y1f >= 0.f && y1f <= (float)(Hc-1)) ? 1.f : 0.f;

        int x0 = min(max((int)x0f, 0), Wc-1);
        int y0 = min(max((int)y0f, 0), Hc-1);
        int x1 = min(max((int)x1f, 0), Wc-1);
        int y1 = min(max((int)y1f, 0), Hc-1);

        float a00 = wx0*wy0*vx0*vy0;
        float a10 = wx1*wy0*vx1*vy0;
        float a01 = wx0*wy1*vx0*vy1;
        float a11 = wx1*wy1*vx1*vy1;

        int o00 = y0*Wc + x0;
        int o10 = y0*Wc + x1;
        int o01 = y1*Wc + x0;
        int o11 = y1*Wc + x1;

        float sim[8];
        #pragma unroll
        for (int g = 0; g < 8; g++) {
            const float4* fg = fbase + (size_t)g*HWc;
            float4 f00 = fg[o00], f10 = fg[o10], f01 = fg[o01], f11 = fg[o11];
            float sx = a00*f00.x + a10*f10.x + a01*f01.x + a11*f11.x;
            float sy = a00*f00.y + a10*f10.y + a01*f01.y + a11*f11.y;
            float sz = a00*f00.z + a10*f10.z + a01*f01.z + a11*f11.z;
            float sw = a00*f00.w + a10*f10.w + a01*f01.w + a11*f11.w;
            float4 r = rf[g];
            sim[g] = (sx*r.x + sy*r.y + sz*r.z + sw*r.w) * 0.25f;
        }

        #pragma unroll
        for (int g = 0; g < 8; g++)
            gs[((size_t)g*Dc + d)*HWc] = sim[g];

        // softmax over G + entropy
        float m = sim[0];
        #pragma unroll
        for (int g = 1; g < 8; g++) m = fmaxf(m, sim[g]);
        float ssum = 0.0f;
        float ex[8];
        #pragma unroll
        for (int g = 0; g < 8; g++) { ex[g] = __expf(sim[g] - m); ssum += ex[g]; }
        float inv_s = 1.0f / ssum;
        float ent = 0.0f;
        #pragma unroll
        for (int g = 0; g < 8; g++) {
            float p = ex[g] * inv_s;
            ent -= p * __logf(p + 1e-7f);
        }

        // 1 -> 16 -> 8 -> 1 MLP (sigmoid deferred: monotone)
        float h1[16];
        #pragma unroll
        for (int j = 0; j < 16; j++) h1[j] = fmaxf(c_pw1[j]*ent + c_pb1[j], 0.0f);
        float h2[8];
        #pragma unroll
        for (int k = 0; k < 8; k++) {
            float t = c_pb2[k];
            #pragma unroll
            for (int j = 0; j < 16; j++) t += c_pw2[k*16 + j] * h1[j];
            h2[k] = fmaxf(t, 0.0f);
        }
        float o3 = c_pb3[0];
        #pragma unroll
        for (int k = 0; k < 8; k++) o3 += c_pw3[k] * h2[k];
        o3max = fmaxf(o3max, o3);
    }

    float vw = 1.0f / (1.0f + __expf(-o3max));
    out_vw[((size_t)b*(Vc-1) + (v-1))*HWc + pix] = vw;
}

// -------- combine: out_sim = sum_v sim_v*vw_v / (sum_v vw_v + eps) ---------
__global__ void combine_kernel(const float* __restrict__ vwbuf,
                               float* __restrict__ out_sim) {
    size_t i4 = (size_t)blockIdx.x * blockDim.x + threadIdx.x;
    if (i4 >= SIMN/4) return;
    size_t idx = i4 * 4;
    int b   = (int)(idx / ((size_t)Gc*Dc*HWc));
    int pix = (int)(idx % HWc);

    float4 acc = make_float4(0.f, 0.f, 0.f, 0.f);
    float4 ws  = make_float4(0.f, 0.f, 0.f, 0.f);
    #pragma unroll
    for (int vi = 0; vi < Vc-1; vi++) {
        float4 vw = *(const float4*)&vwbuf[((size_t)b*(Vc-1) + vi)*HWc + pix];
        float4 s  = *(const float4*)&g_sim[vi][idx];
        acc.x += s.x*vw.x; acc.y += s.y*vw.y; acc.z += s.z*vw.z; acc.w += s.w*vw.w;
        ws.x += vw.x; ws.y += vw.y; ws.z += vw.z; ws.w += vw.w;
    }
    float4 o;
    o.x = acc.x / (ws.x + 1e-6f);
    o.y = acc.y / (ws.y + 1e-6f);
    o.z = acc.z / (ws.z + 1e-6f);
    o.w = acc.w / (ws.w + 1e-6f);
    *(float4*)&out_sim[idx] = o;
}

// ---------------- conv3d 8->8, 3x3x3, pad 1, relu (streaming d) ------------
#define CT 8
__global__ void __launch_bounds__(CT*CT) conv1_kernel(const float* __restrict__ simil) {
    __shared__ float sl[8][CT+2][CT+2];
    int tx = threadIdx.x, ty = threadIdx.y;
    int w0 = blockIdx.x * CT, h0 = blockIdx.y * CT;
    int b = blockIdx.z;
    int tid = ty * CT + tx;

    const float* base = simil + (size_t)b*Gc*Dc*HWc;
    float* outb = g_sim[0] + (size_t)b*8*Dc*HWc;

    float accP[8], accC[8], accN[8];
    #pragma unroll
    for (int o = 0; o < 8; o++) { accP[o] = 0.f; accC[o] = 0.f; accN[o] = 0.f; }

    #pragma unroll 1
    for (int s = 0; s < Dc; s++) {
        __syncthreads();
        for (int idx = tid; idx < 8*(CT+2)*(CT+2); idx += CT*CT) {
            int i  = idx / ((CT+2)*(CT+2));
            int rm = idx % ((CT+2)*(CT+2));
            int hh = rm / (CT+2), ww = rm % (CT+2);
            int gh = h0 + hh - 1, gw = w0 + ww - 1;
            float val = 0.0f;
            if (gh >= 0 && gh < Hc && gw >= 0 && gw < Wc)
                val = base[((size_t)i*Dc + s)*HWc + gh*Wc + gw];
            sl[i][hh][ww] = val;
        }
        __syncthreads();

        #pragma unroll
        for (int i = 0; i < 8; i++) {
            #pragma unroll
            for (int kh = 0; kh < 3; kh++) {
                #pragma unroll
                for (int kw = 0; kw < 3; kw++) {
                    float x = sl[i][ty+kh][tx+kw];
                    int wb = i*27 + kh*3 + kw;
                    #pragma unroll
                    for (int o = 0; o < 8; o++) {
                        accN[o] += x * c_rw1[o*216 + wb];
                        accC[o] += x * c_rw1[o*216 + wb + 9];
                        accP[o] += x * c_rw1[o*216 + wb + 18];
                    }
                }
            }
        }

        if (s >= 1) {
            size_t pb = (size_t)(s-1)*HWc + (h0+ty)*Wc + (w0+tx);
            #pragma unroll
            for (int o = 0; o < 8; o++)
                outb[(size_t)o*Dc*HWc + pb] = fmaxf(accP[o] + c_rb1[o], 0.0f);
        }
        #pragma unroll
        for (int o = 0; o < 8; o++) { accP[o] = accC[o]; accC[o] = accN[o]; accN[o] = 0.f; }
    }
    {
        size_t pb = (size_t)(Dc-1)*HWc + (h0+ty)*Wc + (w0+tx);
        #pragma unroll
        for (int o = 0; o < 8; o++)
            outb[(size_t)o*Dc*HWc + pb] = fmaxf(accP[o] + c_rb1[o], 0.0f);
    }
}

// ---------------- conv3d 8->1, 3x3x3, pad 1 (streaming d) ------------------
__global__ void __launch_bounds__(CT*CT) conv2_kernel(float* __restrict__ out_pvp) {
    __shared__ float sl[8][CT+2][CT+2];
    int tx = threadIdx.x, ty = threadIdx.y;
    int w0 = blockIdx.x * CT, h0 = blockIdx.y * CT;
    int b = blockIdx.z;
    int tid = ty * CT + tx;

    const float* base = g_sim[0] + (size_t)b*8*Dc*HWc;

    float accP = 0.f, accC = 0.f, accN = 0.f;

    #pragma unroll 1
    for (int s = 0; s < Dc; s++) {
        __syncthreads();
        for (int idx = tid; idx < 8*(CT+2)*(CT+2); idx += CT*CT) {
            int i  = idx / ((CT+2)*(CT+2));
            int rm = idx % ((CT+2)*(CT+2));
            int hh = rm / (CT+2), ww = rm % (CT+2);
            int gh = h0 + hh - 1, gw = w0 + ww - 1;
            float val = 0.0f;
            if (gh >= 0 && gh < Hc && gw >= 0 && gw < Wc)
                val = base[((size_t)i*Dc + s)*HWc + gh*Wc + gw];
            sl[i][hh][ww] = val;
        }
        __syncthreads();

        #pragma unroll
        for (int i = 0; i < 8; i++) {
            #pragma unroll
            for (int kh = 0; kh < 3; kh++) {
                #pragma unroll
                for (int kw = 0; kw < 3; kw++) {
                    float x = sl[i][ty+kh][tx+kw];
                    int wb = i*27 + kh*3 + kw;
                    accN += x * c_rw2[wb];
                    accC += x * c_rw2[wb + 9];
                    accP += x * c_rw2[wb + 18];
                }
            }
        }

        if (s >= 1)
            out_pvp[((size_t)b*Dc + (s-1))*HWc + (h0+ty)*Wc + (w0+tx)] = accP + c_rb2[0];
        accP = accC; accC = accN; accN = 0.f;
    }
    out_pvp[((size_t)b*Dc + (Dc-1))*HWc + (h0+ty)*Wc + (w0+tx)] = accP + c_rb2[0];
}

// ---------------- depth softmax + expectation + confidence -----------------
__global__ void final_kernel(const float* __restrict__ pvp,
                             const float* __restrict__ dv,
                             float* __restrict__ depth_out,
                             float* __restrict__ conf_out) {
    int p = blockIdx.x * blockDim.x + threadIdx.x;
    if (p >= BHW) return;
    int b = p / HWc, pix = p % HWc;
    const float* vp  = pvp + (size_t)b*Dc*HWc + pix;
    const float* dvp = dv  + (size_t)b*Dc*HWc + pix;

    float x[Dc];
    float m = -1e30f;
    #pragma unroll
    for (int d = 0; d < Dc; d++) { x[d] = vp[(size_t)d*HWc]; m = fmaxf(m, x[d]); }
    float s = 0.0f;
    #pragma unroll
    for (int d = 0; d < Dc; d++) { x[d] = expf(x[d] - m); s += x[d]; }
    float inv_s = 1.0f / s;
    float depth = 0.0f, dif = 0.0f;
    #pragma unroll
    for (int d = 0; d < Dc; d++) {
        float pd = x[d] * inv_s;
        x[d] = pd;
        depth += pd * dvp[(size_t)d*HWc];
        dif += pd * (float)d;
    }
    int di = min(max((int)dif, 0), Dc-1);
    float c4 = 0.0f;
    #pragma unroll
    for (int d = 0; d < Dc; d++) {
        bool in = (d >= di - 1) && (d <= di + 2);
        c4 += in ? x[d] : 0.0f;
    }
    depth_out[p] = depth;
    conf_out[p] = c4;
}

// ---------------- launch ----------------------------------------------------
extern "C" void kernel_launch(void* const* d_in, const int* in_sizes, int n_in,
                              void* d_out, int out_size) {
    const float* features = (const float*)d_in[0];
    const float* pm       = (const float*)d_in[1];
    const float* dv       = (const float*)d_in[2];

    cudaMemcpyToSymbolAsync(c_rw1, d_in[3], 8*8*27*sizeof(float), 0, cudaMemcpyDeviceToDevice);
    cudaMemcpyToSymbolAsync(c_rb1, d_in[4], 8*sizeof(float),      0, cudaMemcpyDeviceToDevice);
    cudaMemcpyToSymbolAsync(c_rw2, d_in[5], 8*27*sizeof(float),   0, cudaMemcpyDeviceToDevice);
    cudaMemcpyToSymbolAsync(c_rb2, d_in[6], 1*sizeof(float),      0, cudaMemcpyDeviceToDevice);
    cudaMemcpyToSymbolAsync(c_pw1, d_in[7], 16*sizeof(float),     0, cudaMemcpyDeviceToDevice);
    cudaMemcpyToSymbolAsync(c_pb1, d_in[8], 16*sizeof(float),     0, cudaMemcpyDeviceToDevice);
    cudaMemcpyToSymbolAsync(c_pw2, d_in[9], 8*16*sizeof(float),   0, cudaMemcpyDeviceToDevice);
    cudaMemcpyToSymbolAsync(c_pb2, d_in[10], 8*sizeof(float),     0, cudaMemcpyDeviceToDevice);
    cudaMemcpyToSymbolAsync(c_pw3, d_in[11], 8*sizeof(float),     0, cudaMemcpyDeviceToDevice);
    cudaMemcpyToSymbolAsync(c_pb3, d_in[12], 1*sizeof(float),     0, cudaMemcpyDeviceToDevice);

    float* out       = (float*)d_out;
    float* out_depth = out;
    float* out_conf  = out + BHW;
    float* out_vw    = out + 2*BHW;
    float* out_pvp   = out + 2*BHW + (Vc-1)*BHW;
    float* out_sim   = out_pvp + BDHW;

    proj_kernel<<<1, 32>>>(pm);

    {   // transpose features to group-major float4 layout
        dim3 grd(HWc/32, Vc*Bc);
        transpose_kernel<<<grd, 256>>>(features);
    }

    {   // fused warp + sim + entropy MLP + view weight
        dim3 grd(HWc/256, Bc, Vc-1);
        warp_sim_kernel<<<grd, 256>>>(dv, out_vw);
    }

    combine_kernel<<<(SIMN/4 + 255)/256, 256>>>(out_vw, out_sim);

    {
        dim3 blk(CT, CT);
        dim3 grd(Wc/CT, Hc/CT, Bc);
        conv1_kernel<<<grd, blk>>>(out_sim);
        conv2_kernel<<<grd, blk>>>(out_pvp);
    }

    final_kernel<<<(BHW + 255)/256, 256>>>(out_pvp, dv, out_depth, out_conf);
}

// round 4
// speedup vs baseline: 8.5963x; 2.5614x over previous
#include <cuda_runtime.h>
#include <cuda_fp16.h>
#include <math.h>

#define Bc 2
#define Vc 5
#define Cc 32
#define Hc 128
#define Wc 160
#define Dc 32
#define Gc 8
#define HWc (Hc*Wc)            // 20480
#define BHW (Bc*HWc)           // 40960
#define BDHW (Bc*Dc*HWc)       // 1310720
#define SIMN (Bc*Gc*Dc*HWc)    // 10485760

// ---------------- scratch (device globals) ----------------
__device__ __half2 g_simh[(size_t)(Vc-1)*Bc*4*Dc*HWc];   // sim as (g-even,g-odd) half2
__device__ float   g_feat[(size_t)Vc*Bc*Cc*HWc];         // (V,B,G,HW,4)
__device__ float   g_c1[(size_t)Bc*8*Dc*HWc];            // conv1 output
__device__ float   g_ent[(size_t)(Vc-1)*BDHW];           // entropy (slow path only)
__device__ float   g_proj[(Vc-1)*Bc][12];
__device__ float   g_S[4];                               // S, b3, flag

// ---------------- f32x2 helpers ----------------
__device__ __forceinline__ unsigned long long pk2(float lo, float hi) {
    unsigned long long r;
    asm("mov.b64 %0, {%1,%2};" : "=l"(r) : "f"(lo), "f"(hi));
    return r;
}
__device__ __forceinline__ void fma2(unsigned long long& d,
                                     unsigned long long a, unsigned long long b) {
    asm("fma.rn.f32x2 %0, %1, %2, %0;" : "+l"(d) : "l"(a), "l"(b));
}
__device__ __forceinline__ float2 upk2(unsigned long long v) {
    float2 r;
    asm("mov.b64 {%0,%1}, %2;" : "=f"(r.x), "=f"(r.y) : "l"(v));
    return r;
}

// ---------------- projection + MLP-fold setup ----------------
__device__ void combine_mat(const float* pm, double out[16]) {
    const float* e = pm;
    const float* K = pm + 16;
    for (int r = 0; r < 4; r++)
        for (int c = 0; c < 4; c++)
            out[r*4+c] = (double)e[r*4+c];
    for (int r = 0; r < 3; r++)
        for (int c = 0; c < 4; c++) {
            double s = 0.0;
            for (int k = 0; k < 3; k++) s += (double)K[r*4+k] * (double)e[k*4+c];
            out[r*4+c] = s;
        }
}

__device__ void inv4(const double A[16], double Out[16]) {
    double a[4][8];
    for (int r = 0; r < 4; r++)
        for (int c = 0; c < 4; c++) { a[r][c] = A[r*4+c]; a[r][c+4] = (r == c) ? 1.0 : 0.0; }
    for (int col = 0; col < 4; col++) {
        int piv = col; double best = fabs(a[col][col]);
        for (int r = col+1; r < 4; r++) { double v = fabs(a[r][col]); if (v > best) { best = v; piv = r; } }
        if (piv != col)
            for (int c = 0; c < 8; c++) { double t = a[col][c]; a[col][c] = a[piv][c]; a[piv][c] = t; }
        double d = 1.0 / a[col][col];
        for (int c = 0; c < 8; c++) a[col][c] *= d;
        for (int r = 0; r < 4; r++) {
            if (r == col) continue;
            double f = a[r][col];
            for (int c = 0; c < 8; c++) a[r][c] -= f * a[col][c];
        }
    }
    for (int r = 0; r < 4; r++)
        for (int c = 0; c < 4; c++) Out[r*4+c] = a[r][c+4];
}

__global__ void proj_kernel(const float* __restrict__ pm,
                            const float* __restrict__ pw1, const float* __restrict__ pb1,
                            const float* __restrict__ pw2, const float* __restrict__ pb2,
                            const float* __restrict__ pw3, const float* __restrict__ pb3) {
    if (threadIdx.x != 0 || blockIdx.x != 0) return;
    for (int b = 0; b < Bc; b++) {
        double ref[16], ri[16];
        combine_mat(pm + ((size_t)b*Vc + 0)*32, ref);
        inv4(ref, ri);
        for (int v = 1; v < Vc; v++) {
            double Cm[16];
            combine_mat(pm + ((size_t)b*Vc + v)*32, Cm);
            float* P = g_proj[(v-1)*Bc + b];
            for (int r = 0; r < 3; r++) {
                for (int c = 0; c < 4; c++) {
                    double s = 0.0;
                    for (int k = 0; k < 4; k++) s += Cm[r*4+k] * ri[k*4+c];
                    if (c < 3) P[r*3+c] = (float)s;
                    else       P[9+r]  = (float)s;
                }
            }
        }
    }
    // MLP fold: valid when all hidden biases are exactly zero
    float flag = 1.0f;
    for (int j = 0; j < 16; j++) if (pb1[j] != 0.0f) flag = 0.0f;
    for (int k = 0; k < 8;  k++) if (pb2[k] != 0.0f) flag = 0.0f;
    float S = 0.0f;
    for (int k = 0; k < 8; k++) {
        float u = 0.0f;
        for (int j = 0; j < 16; j++) u += pw2[k*16+j] * fmaxf(pw1[j], 0.0f);
        S += pw3[k] * fmaxf(u, 0.0f);
    }
    g_S[0] = S; g_S[1] = pb3[0]; g_S[2] = flag;
}

// --------- feature transpose (V,B,C,HW) -> (V,B,G,HW,4) float4 groups -----
__global__ void __launch_bounds__(256) transpose_kernel(const float* __restrict__ f) {
    __shared__ float t[32][33];
    int vb  = blockIdx.y;
    int hw0 = blockIdx.x * 32;
    int tid = threadIdx.x;
    #pragma unroll
    for (int i = 0; i < 4; i++) {
        int idx = tid + i*256;
        int ch = idx / 32, hw = idx % 32;
        t[ch][hw] = f[((size_t)vb*Cc + ch)*HWc + hw0 + hw];
    }
    __syncthreads();
    int g = tid / 32, hw = tid % 32;
    float4 o = make_float4(t[4*g+0][hw], t[4*g+1][hw], t[4*g+2][hw], t[4*g+3][hw]);
    ((float4*)g_feat)[((size_t)vb*Gc + g)*HWc + hw0 + hw] = o;
}

// ------- fused warp + group correlation + entropy + folded MLP -------------
__global__ void __launch_bounds__(256) warp_sim_kernel(const float* __restrict__ dv,
                                                       float* __restrict__ out_vw) {
    int pix = blockIdx.x * 256 + threadIdx.x;
    int b = blockIdx.y;
    int v = blockIdx.z + 1;
    int w = pix % Wc, h = pix / Wc;

    const float* P = g_proj[(v-1)*Bc + b];
    float xf = (float)w, yf = (float)h;
    float rx = P[0]*xf + P[1]*yf + P[2];
    float ry = P[3]*xf + P[4]*yf + P[5];
    float rz = P[6]*xf + P[7]*yf + P[8];

    const float4* refb = ((const float4*)g_feat) + (size_t)b*Gc*HWc + pix;
    float4 rf[8];
    #pragma unroll
    for (int g = 0; g < 8; g++) rf[g] = refb[(size_t)g*HWc];

    const float4* fbase = ((const float4*)g_feat) + (size_t)(v*Bc + b)*Gc*HWc;
    __half2* gs = g_simh + ((size_t)((v-1)*Bc + b)*4)*Dc*HWc + pix;

    float S = g_S[0], b3 = g_S[1];
    bool slow = (g_S[2] == 0.0f);
    float entmin = 1e30f, entmax = -1e30f;

    #pragma unroll 1
    for (int d = 0; d < Dc; d++) {
        float dep = dv[((size_t)(b*Dc + d))*HWc + pix];
        float px = rx*dep + P[9];
        float py = ry*dep + P[10];
        float pz = rz*dep + P[11];
        float iz = 1.0f / pz;
        float x = px * iz;
        float y = py * iz;

        float x0f = floorf(x), y0f = floorf(y);
        float wx1 = x - x0f, wy1 = y - y0f;
        float wx0 = 1.0f - wx1, wy0 = 1.0f - wy1;
        float x1f = x0f + 1.0f, y1f = y0f + 1.0f;

        float vx0 = (x0f >= 0.f && x0f <= (float)(Wc-1)) ? 1.f : 0.f;
        float vx1 = (x1f >= 0.f && x1f <= (float)(Wc-1)) ? 1.f : 0.f;
        float vy0 = (y0f >= 0.f && y0f <= (float)(Hc-1)) ? 1.f : 0.f;
        float vy1 = (y1f >= 0.f && y1f <= (float)(Hc-1)) ? 1.f : 0.f;

        int x0 = min(max((int)x0f, 0), Wc-1);
        int y0 = min(max((int)y0f, 0), Hc-1);
        int x1 = min(max((int)x1f, 0), Wc-1);
        int y1 = min(max((int)y1f, 0), Hc-1);

        float a00 = wx0*wy0*vx0*vy0;
        float a10 = wx1*wy0*vx1*vy0;
        float a01 = wx0*wy1*vx0*vy1;
        float a11 = wx1*wy1*vx1*vy1;

        int o00 = y0*Wc + x0;
        int o10 = y0*Wc + x1;
        int o01 = y1*Wc + x0;
        int o11 = y1*Wc + x1;

        float sim[8];
        #pragma unroll
        for (int g = 0; g < 8; g++) {
            const float4* fg = fbase + (size_t)g*HWc;
            float4 f00 = fg[o00], f10 = fg[o10], f01 = fg[o01], f11 = fg[o11];
            float sx = a00*f00.x + a10*f10.x + a01*f01.x + a11*f11.x;
            float sy = a00*f00.y + a10*f10.y + a01*f01.y + a11*f11.y;
            float sz = a00*f00.z + a10*f10.z + a01*f01.z + a11*f11.z;
            float sw = a00*f00.w + a10*f10.w + a01*f01.w + a11*f11.w;
            float4 r = rf[g];
            sim[g] = (sx*r.x + sy*r.y + sz*r.z + sw*r.w) * 0.25f;
        }

        #pragma unroll
        for (int j = 0; j < 4; j++)
            gs[((size_t)j*Dc + d)*HWc] = __floats2half2_rn(sim[2*j], sim[2*j+1]);

        float m = sim[0];
        #pragma unroll
        for (int g = 1; g < 8; g++) m = fmaxf(m, sim[g]);
        float ssum = 0.0f;
        float ex[8];
        #pragma unroll
        for (int g = 0; g < 8; g++) { ex[g] = __expf(sim[g] - m); ssum += ex[g]; }
        float inv_s = 1.0f / ssum;
        float ent = 0.0f;
        #pragma unroll
        for (int g = 0; g < 8; g++) {
            float p = ex[g] * inv_s;
            ent -= p * __logf(p + 1e-7f);
        }
        entmin = fminf(entmin, ent);
        entmax = fmaxf(entmax, ent);
        if (slow)
            g_ent[((size_t)((v-1)*Bc + b)*Dc + d)*HWc + pix] = ent;
    }

    float o3m = fmaxf(S*entmax, S*entmin) + b3;
    out_vw[((size_t)b*(Vc-1) + (v-1))*HWc + pix] = 1.0f / (1.0f + __expf(-o3m));
}

// ------- slow-path fixup (only if hidden biases nonzero) -------------------
__global__ void vw_fix_kernel(const float* __restrict__ pw1, const float* __restrict__ pb1,
                              const float* __restrict__ pw2, const float* __restrict__ pb2,
                              const float* __restrict__ pw3, const float* __restrict__ pb3,
                              float* __restrict__ out_vw) {
    if (g_S[2] != 0.0f) return;
    int t = blockIdx.x * blockDim.x + threadIdx.x;
    if (t >= (Vc-1)*BHW) return;
    int pix = t % HWc;
    int b   = (t / HWc) % Bc;
    int vi  = t / BHW;
    float o3max = -1e30f;
    for (int d = 0; d < Dc; d++) {
        float ent = g_ent[((size_t)(vi*Bc + b)*Dc + d)*HWc + pix];
        float h1[16];
        for (int j = 0; j < 16; j++) h1[j] = fmaxf(pw1[j]*ent + pb1[j], 0.0f);
        float o3 = pb3[0];
        for (int k = 0; k < 8; k++) {
            float u = pb2[k];
            for (int j = 0; j < 16; j++) u += pw2[k*16+j]*h1[j];
            o3 += pw3[k] * fmaxf(u, 0.0f);
        }
        o3max = fmaxf(o3max, o3);
    }
    out_vw[((size_t)b*(Vc-1) + vi)*HWc + pix] = 1.0f / (1.0f + __expf(-o3max));
}

// -------- combine: out_sim = sum_v sim_v*vw_v / (sum_v vw_v + eps) ---------
__global__ void __launch_bounds__(256) combine_kernel(const float* __restrict__ vwbuf,
                                                      float* __restrict__ out_sim) {
    int t = blockIdx.x * 256 + threadIdx.x;
    const int NP = HWc/4;
    int pix0 = (t % NP) * 4;
    int d  = (t / NP) % Dc;
    int gp = (t / (NP*Dc)) % 4;
    int b  =  t / (NP*Dc*4);

    float4 aA = make_float4(0,0,0,0), aB = make_float4(0,0,0,0);
    float4 ws = make_float4(0,0,0,0);
    #pragma unroll
    for (int v = 0; v < Vc-1; v++) {
        float4 vw4 = *(const float4*)&vwbuf[((size_t)b*(Vc-1) + v)*HWc + pix0];
        uint4 raw = *(const uint4*)&g_simh[(((size_t)(v*Bc + b)*4 + gp)*Dc + d)*HWc + pix0];
        float2 s0 = __half22float2(*(__half2*)&raw.x);
        float2 s1 = __half22float2(*(__half2*)&raw.y);
        float2 s2 = __half22float2(*(__half2*)&raw.z);
        float2 s3 = __half22float2(*(__half2*)&raw.w);
        aA.x += s0.x*vw4.x; aB.x += s0.y*vw4.x;
        aA.y += s1.x*vw4.y; aB.y += s1.y*vw4.y;
        aA.z += s2.x*vw4.z; aB.z += s2.y*vw4.z;
        aA.w += s3.x*vw4.w; aB.w += s3.y*vw4.w;
        ws.x += vw4.x; ws.y += vw4.y; ws.z += vw4.z; ws.w += vw4.w;
    }
    float4 iw = make_float4(1.f/(ws.x+1e-6f), 1.f/(ws.y+1e-6f),
                            1.f/(ws.z+1e-6f), 1.f/(ws.w+1e-6f));
    float4 oA = make_float4(aA.x*iw.x, aA.y*iw.y, aA.z*iw.z, aA.w*iw.w);
    float4 oB = make_float4(aB.x*iw.x, aB.y*iw.y, aB.z*iw.z, aB.w*iw.w);
    *(float4*)&out_sim[((size_t)(b*8 + 2*gp  )*Dc + d)*HWc + pix0] = oA;
    *(float4*)&out_sim[((size_t)(b*8 + 2*gp+1)*Dc + d)*HWc + pix0] = oB;
}

// ---------------- conv3d 8->8, 3x3x3, pad 1, relu --------------------------
// block: 128 threads, tile 32w x 16h, 4 px/thread (2 f32x2 pairs), D chunk 8
#define TW 32
#define TH 16
#define DCH 8
__global__ void __launch_bounds__(128) conv1_kernel(const float* __restrict__ simil,
                                                    const float* __restrict__ w1,
                                                    const float* __restrict__ b1) {
    __shared__ float  xs[8*18*34];
    __shared__ float4 wsm[8*3*8*3];   // [i][kh][o][kd] -> (kw0,kw1,kw2,-)
    __shared__ float  bsm[8];
    int tid = threadIdx.x;
    int tx = tid & 7, ty = tid >> 3;
    int w0 = blockIdx.x * TW, h0 = blockIdx.y * TH;
    int b = blockIdx.z >> 2, s0 = (blockIdx.z & 3) * DCH;
    int lx = tx * 4;

    for (int idx = tid; idx < 8*3*8*3; idx += 128) {
        int i = idx / 72, r = idx % 72;
        int kh = r / 24, r2 = r % 24;
        int o = r2 / 3, kd = r2 % 3;
        const float* wp = w1 + o*216 + i*27 + kd*9 + kh*3;
        wsm[idx] = make_float4(wp[0], wp[1], wp[2], 0.f);
    }
    if (tid < 8) bsm[tid] = b1[tid];

    const float* base = simil + (size_t)b*8*Dc*HWc;
    float* outb = g_c1 + (size_t)b*8*Dc*HWc;

    unsigned long long aP[16], aC[16], aN[16];
    #pragma unroll
    for (int k = 0; k < 16; k++) { aP[k] = 0ull; aC[k] = 0ull; aN[k] = 0ull; }

    #pragma unroll 1
    for (int s = s0-1; s <= s0+DCH; s++) {
        bool have = (s >= 0 && s < Dc);
        __syncthreads();
        if (have) {
            for (int idx = tid; idx < 8*18*34; idx += 128) {
                int i = idx / (18*34), r = idx % (18*34);
                int hh = r / 34, ww = r % 34;
                int gh = h0 + hh - 1, gw = w0 + ww - 1;
                float val = 0.0f;
                if ((unsigned)gh < (unsigned)Hc && (unsigned)gw < (unsigned)Wc)
                    val = base[((size_t)i*Dc + s)*HWc + gh*Wc + gw];
                xs[idx] = val;
            }
        }
        __syncthreads();
        if (have) {
            #pragma unroll 1
            for (int i = 0; i < 8; i++) {
                #pragma unroll
                for (int kh = 0; kh < 3; kh++) {
                    const float* row = &xs[(i*18 + ty + kh)*34 + lx];
                    float2 q0 = *(const float2*)(row);
                    float2 q1 = *(const float2*)(row+2);
                    float2 q2 = *(const float2*)(row+4);
                    unsigned long long A0 = pk2(q0.x, q0.y);
                    unsigned long long B0 = pk2(q1.x, q1.y);
                    unsigned long long A1 = pk2(q0.y, q1.x);
                    unsigned long long B1 = pk2(q1.y, q2.x);
                    unsigned long long C0 = pk2(q2.x, q2.y);
                    const float4* wp = &wsm[(i*3 + kh)*24];
                    #pragma unroll
                    for (int o = 0; o < 8; o++) {
                        float4 wn = wp[o*3+0];
                        float4 wc = wp[o*3+1];
                        float4 wv = wp[o*3+2];
                        unsigned long long t;
                        t = pk2(wn.x,wn.x); fma2(aN[2*o],t,A0); fma2(aN[2*o+1],t,B0);
                        t = pk2(wn.y,wn.y); fma2(aN[2*o],t,A1); fma2(aN[2*o+1],t,B1);
                        t = pk2(wn.z,wn.z); fma2(aN[2*o],t,B0); fma2(aN[2*o+1],t,C0);
                        t = pk2(wc.x,wc.x); fma2(aC[2*o],t,A0); fma2(aC[2*o+1],t,B0);
                        t = pk2(wc.y,wc.y); fma2(aC[2*o],t,A1); fma2(aC[2*o+1],t,B1);
                        t = pk2(wc.z,wc.z); fma2(aC[2*o],t,B0); fma2(aC[2*o+1],t,C0);
                        t = pk2(wv.x,wv.x); fma2(aP[2*o],t,A0); fma2(aP[2*o+1],t,B0);
                        t = pk2(wv.y,wv.y); fma2(aP[2*o],t,A1); fma2(aP[2*o+1],t,B1);
                        t = pk2(wv.z,wv.z); fma2(aP[2*o],t,B0); fma2(aP[2*o+1],t,C0);
                    }
                }
            }
        }
        int so = s - 1;
        if (so >= s0 && so < s0 + DCH) {
            size_t pb = (size_t)so*HWc + (h0+ty)*Wc + (w0+lx);
            #pragma unroll
            for (int o = 0; o < 8; o++) {
                float2 pA = upk2(aP[2*o]), pB = upk2(aP[2*o+1]);
                float bb = bsm[o];
                float4 ov = make_float4(fmaxf(pA.x+bb,0.f), fmaxf(pA.y+bb,0.f),
                                        fmaxf(pB.x+bb,0.f), fmaxf(pB.y+bb,0.f));
                *(float4*)&outb[(size_t)o*Dc*HWc + pb] = ov;
            }
        }
        #pragma unroll
        for (int k = 0; k < 16; k++) { aP[k] = aC[k]; aC[k] = aN[k]; aN[k] = 0ull; }
    }
}

// ---------------- conv3d 8->1, 3x3x3, pad 1 --------------------------------
__global__ void __launch_bounds__(128) conv2_kernel(const float* __restrict__ w2,
                                                    const float* __restrict__ b2,
                                                    float* __restrict__ out_pvp) {
    __shared__ float  xs[8*18*34];
    __shared__ float4 wsm[8*3*3];   // [i][kh][kd] -> (kw0,kw1,kw2,-)
    __shared__ float  bias;
    int tid = threadIdx.x;
    int tx = tid & 7, ty = tid >> 3;
    int w0 = blockIdx.x * TW, h0 = blockIdx.y * TH;
    int b = blockIdx.z >> 2, s0 = (blockIdx.z & 3) * DCH;
    int lx = tx * 4;

    for (int idx = tid; idx < 8*3*3; idx += 128) {
        int i = idx / 9, r = idx % 9;
        int kh = r / 3, kd = r % 3;
        const float* wp = w2 + i*27 + kd*9 + kh*3;
        wsm[idx] = make_float4(wp[0], wp[1], wp[2], 0.f);
    }
    if (tid == 0) bias = b2[0];

    const float* base = g_c1 + (size_t)b*8*Dc*HWc;

    unsigned long long aP[2], aC[2], aN[2];
    aP[0]=aP[1]=aC[0]=aC[1]=aN[0]=aN[1]=0ull;

    #pragma unroll 1
    for (int s = s0-1; s <= s0+DCH; s++) {
        bool have = (s >= 0 && s < Dc);
        __syncthreads();
        if (have) {
            for (int idx = tid; idx < 8*18*34; idx += 128) {
                int i = idx / (18*34), r = idx % (18*34);
                int hh = r / 34, ww = r % 34;
                int gh = h0 + hh - 1, gw = w0 + ww - 1;
                float val = 0.0f;
                if ((unsigned)gh < (unsigned)Hc && (unsigned)gw < (unsigned)Wc)
                    val = base[((size_t)i*Dc + s)*HWc + gh*Wc + gw];
                xs[idx] = val;
            }
        }
        __syncthreads();
        if (have) {
            #pragma unroll 1
            for (int i = 0; i < 8; i++) {
                #pragma unroll
                for (int kh = 0; kh < 3; kh++) {
                    const float* row = &xs[(i*18 + ty + kh)*34 + lx];
                    float2 q0 = *(const float2*)(row);
                    float2 q1 = *(const float2*)(row+2);
                    float2 q2 = *(const float2*)(row+4);
                    unsigned long long A0 = pk2(q0.x, q0.y);
                    unsigned long long B0 = pk2(q1.x, q1.y);
                    unsigned long long A1 = pk2(q0.y, q1.x);
                    unsigned long long B1 = pk2(q1.y, q2.x);
                    unsigned long long C0 = pk2(q2.x, q2.y);
                    float4 wn = wsm[(i*3+kh)*3+0];
                    float4 wc = wsm[(i*3+kh)*3+1];
                    float4 wv = wsm[(i*3+kh)*3+2];
                    unsigned long long t;
                    t = pk2(wn.x,wn.x); fma2(aN[0],t,A0); fma2(aN[1],t,B0);
                    t = pk2(wn.y,wn.y); fma2(aN[0],t,A1); fma2(aN[1],t,B1);
                    t = pk2(wn.z,wn.z); fma2(aN[0],t,B0); fma2(aN[1],t,C0);
                    t = pk2(wc.x,wc.x); fma2(aC[0],t,A0); fma2(aC[1],t,B0);
                    t = pk2(wc.y,wc.y); fma2(aC[0],t,A1); fma2(aC[1],t,B1);
                    t = pk2(wc.z,wc.z); fma2(aC[0],t,B0); fma2(aC[1],t,C0);
                    t = pk2(wv.x,wv.x); fma2(aP[0],t,A0); fma2(aP[1],t,B0);
                    t = pk2(wv.y,wv.y); fma2(aP[0],t,A1); fma2(aP[1],t,B1);
                    t = pk2(wv.z,wv.z); fma2(aP[0],t,B0); fma2(aP[1],t,C0);
                }
            }
        }
        int so = s - 1;
        if (so >= s0 && so < s0 + DCH) {
            float2 pA = upk2(aP[0]), pB = upk2(aP[1]);
            float4 ov = make_float4(pA.x+bias, pA.y+bias, pB.x+bias, pB.y+bias);
            *(float4*)&out_pvp[((size_t)b*Dc + so)*HWc + (h0+ty)*Wc + (w0+lx)] = ov;
        }
        aP[0]=aC[0]; aP[1]=aC[1]; aC[0]=aN[0]; aC[1]=aN[1]; aN[0]=0ull; aN[1]=0ull;
    }
}

// ---------------- depth softmax + expectation + confidence -----------------
__global__ void final_kernel(const float* __restrict__ pvp,
                             const float* __restrict__ dv,
                             float* __restrict__ depth_out,
                             float* __restrict__ conf_out) {
    int p = blockIdx.x * blockDim.x + threadIdx.x;
    if (p >= BHW) return;
    int b = p / HWc, pix = p % HWc;
    const float* vp  = pvp + (size_t)b*Dc*HWc + pix;
    const float* dvp = dv  + (size_t)b*Dc*HWc + pix;

    float x[Dc];
    float m = -1e30f;
    #pragma unroll
    for (int d = 0; d < Dc; d++) { x[d] = vp[(size_t)d*HWc]; m = fmaxf(m, x[d]); }
    float s = 0.0f;
    #pragma unroll
    for (int d = 0; d < Dc; d++) { x[d] = __expf(x[d] - m); s += x[d]; }
    float inv_s = 1.0f / s;
    float depth = 0.0f, dif = 0.0f;
    #pragma unroll
    for (int d = 0; d < Dc; d++) {
        float pd = x[d] * inv_s;
        x[d] = pd;
        depth += pd * dvp[(size_t)d*HWc];
        dif += pd * (float)d;
    }
    int di = min(max((int)dif, 0), Dc-1);
    float c4 = 0.0f;
    #pragma unroll
    for (int d = 0; d < Dc; d++) {
        bool in = (d >= di - 1) && (d <= di + 2);
        c4 += in ? x[d] : 0.0f;
    }
    depth_out[p] = depth;
    conf_out[p] = c4;
}

// ---------------- launch ----------------------------------------------------
extern "C" void kernel_launch(void* const* d_in, const int* in_sizes, int n_in,
                              void* d_out, int out_size) {
    const float* features = (const float*)d_in[0];
    const float* pm       = (const float*)d_in[1];
    const float* dv       = (const float*)d_in[2];
    const float* rw1      = (const float*)d_in[3];
    const float* rb1      = (const float*)d_in[4];
    const float* rw2      = (const float*)d_in[5];
    const float* rb2      = (const float*)d_in[6];
    const float* pw1      = (const float*)d_in[7];
    const float* pb1      = (const float*)d_in[8];
    const float* pw2      = (const float*)d_in[9];
    const float* pb2      = (const float*)d_in[10];
    const float* pw3      = (const float*)d_in[11];
    const float* pb3      = (const float*)d_in[12];

    float* out       = (float*)d_out;
    float* out_depth = out;
    float* out_conf  = out + BHW;
    float* out_vw    = out + 2*BHW;
    float* out_pvp   = out + 2*BHW + (Vc-1)*BHW;
    float* out_sim   = out_pvp + BDHW;

    proj_kernel<<<1, 32>>>(pm, pw1, pb1, pw2, pb2, pw3, pb3);

    {
        dim3 grd(HWc/32, Vc*Bc);
        transpose_kernel<<<grd, 256>>>(features);
    }
    {
        dim3 grd(HWc/256, Bc, Vc-1);
        warp_sim_kernel<<<grd, 256>>>(dv, out_vw);
    }
    vw_fix_kernel<<<((Vc-1)*BHW + 255)/256, 256>>>(pw1, pb1, pw2, pb2, pw3, pb3, out_vw);

    combine_kernel<<<(Bc*4*Dc*(HWc/4))/256, 256>>>(out_vw, out_sim);

    {
        dim3 blk(128);
        dim3 grd(Wc/TW, Hc/TH, Bc*(Dc/DCH));
        conv1_kernel<<<grd, blk>>>(out_sim, rw1, rb1);
        conv2_kernel<<<grd, blk>>>(rw2, rb2, out_pvp);
    }

    final_kernel<<<(BHW + 255)/256, 256>>>(out_pvp, dv, out_depth, out_conf);
}